// round 5
// baseline (speedup 1.0000x reference)
#include <cuda_runtime.h>
#include <cuda_bf16.h>
#include <stdint.h>

#define NN 8192
#define DD 128
#define WORDS_PER_ROW 256          // 8192 bits / 32
#define MAXNNZ 128                 // per-row capacity (mean ~32; Poisson tail safe)

// -------- scratch (no allocations allowed) --------
__device__ __align__(16) uint32_t g_mask[NN * WORDS_PER_ROW];   // 8 MB adjacency bitmask (edges only, no eye)
__device__ __align__(16) float    g_dis[NN];                    // d^{-1/2}
__device__ __align__(16) float    g_ys[NN * DD];                // ys[j] = dis[j] * (x @ W^T)[j]
__device__ int g_is64;                                          // edge_index dtype flag (auto-detected)

// K0: detect int64 vs int32 edge_index. Values < 8192 -> for int64 every odd 32-bit word is 0.
// Parallel: 128 threads, block-wide OR, one write. (Previous serial version cost ~10us.)
__global__ void k_detect(const uint32_t* __restrict__ raw) {
    int t = threadIdx.x;
    int nz = (raw[2 * t + 1] != 0u);
    int any = __syncthreads_or(nz);
    if (t == 0) g_is64 = !any;
}

// K1: zero the bitmask (must rerun every graph replay)
__global__ void k_zero_mask() {
    uint4* p = reinterpret_cast<uint4*>(g_mask);
    int total = NN * WORDS_PER_ROW / 4;
    for (int i = blockIdx.x * blockDim.x + threadIdx.x; i < total; i += gridDim.x * blockDim.x)
        p[i] = make_uint4(0u, 0u, 0u, 0u);
}

// K2: scatter edges into the bitmask (atomicOr dedups for free). Indices masked -> can never fault.
__global__ void k_scatter(const void* __restrict__ eiraw, int E) {
    int e = blockIdx.x * blockDim.x + threadIdx.x;
    if (e >= E) return;
    int r, c;
    if (g_is64) {
        const long long* ei = (const long long*)eiraw;
        r = (int)ei[e];
        c = (int)ei[E + e];
    } else {
        const int* ei = (const int*)eiraw;
        r = ei[e];
        c = ei[E + e];
    }
    r &= (NN - 1);
    c &= (NN - 1);
    atomicOr(&g_mask[r * WORDS_PER_ROW + (c >> 5)], 1u << (c & 31));
}

// K3: pure popcount degree pass -> d^{-1/2}. Warp per row; lane loads 2x uint4 (32B contiguous).
// No scans, no extraction: streaming-bound (~8MB read).
__global__ void k_degree() {
    int gwarp = (blockIdx.x * blockDim.x + threadIdx.x) >> 5;
    int lane  = threadIdx.x & 31;
    if (gwarp >= NN) return;
    const uint4* row = reinterpret_cast<const uint4*>(g_mask + gwarp * WORDS_PER_ROW);
    uint4 a = row[lane * 2];
    uint4 b = row[lane * 2 + 1];
    int c = __popc(a.x) + __popc(a.y) + __popc(a.z) + __popc(a.w)
          + __popc(b.x) + __popc(b.y) + __popc(b.z) + __popc(b.w);
    c = __reduce_add_sync(0xFFFFFFFFu, c);
    if (lane == 0) {
        // degree = popcount + 1 (the +eye; self-edge bit already in popc -> diag 2 handled downstream)
        g_dis[gwarp] = rsqrtf((float)(c + 1));
    }
}

// K4: ys = diag(dis) * (x @ W^T).  M=8192, N=128, K=128 fp32.
// Block: 128 threads (32x4); each thread: 4 features x 8 rows register tile.
__global__ void k_gemm_xw(const float* __restrict__ x, const float* __restrict__ W) {
    __shared__ float sW[64 * 129];   // sW[k*129 + f] : conflict-free
    __shared__ float sx[32 * 64];    // sx[r*64 + k]  : broadcast reads
    int t  = threadIdx.x;
    int tx = t & 31;                 // feature lane
    int ty = t >> 5;                 // row group
    int r0 = blockIdx.x * 32;

    float acc[4][8];
    #pragma unroll
    for (int q = 0; q < 4; q++)
        #pragma unroll
        for (int p = 0; p < 8; p++) acc[q][p] = 0.f;

    for (int ch = 0; ch < 2; ch++) {
        __syncthreads();
        for (int i = t; i < 128 * 64; i += 128) {       // sW[k][f] = W[f][ch*64+k]
            int f = i >> 6, k = i & 63;
            sW[k * 129 + f] = W[f * 128 + ch * 64 + k];
        }
        for (int i = t; i < 32 * 64; i += 128) {        // sx[r][k] = x[r0+r][ch*64+k]
            int r = i >> 6, k = i & 63;
            sx[r * 64 + k] = x[(r0 + r) * 128 + ch * 64 + k];
        }
        __syncthreads();
        #pragma unroll 8
        for (int k = 0; k < 64; k++) {
            float wv[4];
            #pragma unroll
            for (int q = 0; q < 4; q++) wv[q] = sW[k * 129 + tx + 32 * q];
            #pragma unroll
            for (int p = 0; p < 8; p++) {
                float xv = sx[(ty + 4 * p) * 64 + k];
                #pragma unroll
                for (int q = 0; q < 4; q++) acc[q][p] += xv * wv[q];
            }
        }
    }
    #pragma unroll
    for (int p = 0; p < 8; p++) {
        int r = r0 + ty + 4 * p;
        float d = g_dis[r];
        #pragma unroll
        for (int q = 0; q < 4; q++)
            g_ys[r * 128 + tx + 32 * q] = d * acc[q][p];
    }
}

// K5: fused extract + aggregate.  Block(128) per row i, thread t = feature.
// Threads scan 2 mask words each into a shared neighbor list (order irrelevant: it's a sum),
// then gather-sum ys rows. out[i] = dis[i] * (sum_j ys[j] + ys[i]) + b.
__global__ void k_aggregate(const float* __restrict__ bias, float* __restrict__ out) {
    int i = blockIdx.x;
    int t = threadIdx.x;
    __shared__ int sj[MAXNNZ];
    __shared__ int s_cnt;
    if (t == 0) s_cnt = 0;
    __syncthreads();

    // inline bit extraction: thread t handles words 2t, 2t+1 (coalesced uint2)
    const uint2 w2 = reinterpret_cast<const uint2*>(g_mask + i * WORDS_PER_ROW)[t];
    uint32_t w;
    w = w2.x;
    while (w) {
        int b = __ffs(w) - 1; w &= w - 1;
        int p = atomicAdd(&s_cnt, 1);
        if (p < MAXNNZ) sj[p] = t * 64 + b;
    }
    w = w2.y;
    while (w) {
        int b = __ffs(w) - 1; w &= w - 1;
        int p = atomicAdd(&s_cnt, 1);
        if (p < MAXNNZ) sj[p] = t * 64 + 32 + b;
    }
    __syncthreads();
    int nn = s_cnt < MAXNNZ ? s_cnt : MAXNNZ;

    float acc = g_ys[i * 128 + t];     // +eye diagonal term (self-edge bit in list -> diag 2 correct)
    int n = 0;
    for (; n + 4 <= nn; n += 4) {
        int j0 = sj[n], j1 = sj[n + 1], j2 = sj[n + 2], j3 = sj[n + 3];
        float a0 = g_ys[j0 * 128 + t];
        float a1 = g_ys[j1 * 128 + t];
        float a2 = g_ys[j2 * 128 + t];
        float a3 = g_ys[j3 * 128 + t];
        acc += (a0 + a1) + (a2 + a3);
    }
    for (; n < nn; n++) acc += g_ys[sj[n] * 128 + t];
    out[i * 128 + t] = g_dis[i] * acc + bias[t];
}

extern "C" void kernel_launch(void* const* d_in, const int* in_sizes, int n_in,
                              void* d_out, int out_size) {
    const float* x  = (const float*)d_in[0];
    const void*  ei = d_in[1];
    const float* W  = (const float*)d_in[2];
    const float* b  = (const float*)d_in[3];
    float* out = (float*)d_out;
    int E = in_sizes[1] / 2;   // element count / 2, dtype-independent

    k_detect<<<1, 128>>>((const uint32_t*)ei);
    k_zero_mask<<<512, 256>>>();
    k_scatter<<<(E + 255) / 256, 256>>>(ei, E);
    k_degree<<<NN / 8, 256>>>();                    // 8 warps/block, warp per row
    k_gemm_xw<<<NN / 32, 128>>>(x, W);
    k_aggregate<<<NN, 128>>>(b, out);
}